// round 13
// baseline (speedup 1.0000x reference)
#include <cuda_runtime.h>
#include <cuda_bf16.h>
#include <cstdint>

// Problem constants
#define N_ROWS 131072
#define DDIM   1024
#define KCENT  256
#define M_TILE 64                    // rows per CTA
#define KCHUNK 64                    // bf16 elems per D-chunk (128 B rows)
#define NCHUNKS (DDIM / KCHUNK)      // 16

#define A_BYTES (M_TILE * 128)       // 8192 (one A stage)
#define SM_NORM (2 * A_BYTES)        // float[64]
#define SM_PART (SM_NORM + 256)      // float[4*64]
#define SM_INV  (SM_PART + 1024)     // float[64]
#define SMEM_TOTAL (SM_INV + 256)

// Normalized centroids in mma-fragment order (verified R10/R11):
// uint4 index = step*512 + ntpair*32 + lane   (step = ch*4 + kk, 0..63)
__device__ uint4 g_bf[16 * 4 * 16 * 32];   // 512 KB

// ---------------------------------------------------------------------------
// PTX helpers
// ---------------------------------------------------------------------------
__device__ __forceinline__ unsigned smem_u32(const void* p) {
    return (unsigned)__cvta_generic_to_shared(p);
}
__device__ __forceinline__ void ldmatrix_x4(unsigned r[4], unsigned addr) {
    asm volatile("ldmatrix.sync.aligned.m8n8.x4.shared.b16 {%0,%1,%2,%3}, [%4];"
                 : "=r"(r[0]), "=r"(r[1]), "=r"(r[2]), "=r"(r[3]) : "r"(addr));
}
__device__ __forceinline__ void mma_16816(float d[4], const unsigned a[4],
                                          unsigned b0, unsigned b1) {
    asm volatile(
        "mma.sync.aligned.m16n8k16.row.col.f32.bf16.bf16.f32 "
        "{%0,%1,%2,%3}, {%4,%5,%6,%7}, {%8,%9}, {%0,%1,%2,%3};"
        : "+f"(d[0]), "+f"(d[1]), "+f"(d[2]), "+f"(d[3])
        : "r"(a[0]), "r"(a[1]), "r"(a[2]), "r"(a[3]), "r"(b0), "r"(b1));
}
__device__ __forceinline__ void sts128(unsigned addr, uint4 v) {
    asm volatile("st.shared.v4.b32 [%0], {%1, %2, %3, %4};"
                 :: "r"(addr), "r"(v.x), "r"(v.y), "r"(v.z), "r"(v.w) : "memory");
}

// ---------------------------------------------------------------------------
// Prepass: normalize centroids (fp32) and scatter into fragment layout.
// ---------------------------------------------------------------------------
__global__ void centroid_prep_kernel(const float* __restrict__ cent) {
    int n = blockIdx.x;
    int t = threadIdx.x;
    const float4 v = reinterpret_cast<const float4*>(cent + (size_t)n * DDIM)[t];
    float s = v.x * v.x + v.y * v.y + v.z * v.z + v.w * v.w;
    #pragma unroll
    for (int o = 16; o; o >>= 1) s += __shfl_xor_sync(0xFFFFFFFFu, s, o);
    __shared__ float ws[8];
    __shared__ float s_inv;
    if ((t & 31) == 0) ws[t >> 5] = s;
    __syncthreads();
    if (t == 0) {
        float tot = 0.f;
        #pragma unroll
        for (int i = 0; i < 8; i++) tot += ws[i];
        s_inv = 1.0f / fmaxf(sqrtf(tot), 1e-8f);
    }
    __syncthreads();
    const float iv = s_inv;
    float vals[4] = {v.x * iv, v.y * iv, v.z * iv, v.w * iv};
    char* base = reinterpret_cast<char*>(g_bf);
    #pragma unroll
    for (int j = 0; j < 4; j++) {
        int k = t * 4 + j;
        unsigned off =
            (((((unsigned)(k >> 6) * 4 + ((k >> 4) & 3)) * 16 + (n >> 4)) * 32
              + ((n & 7) * 4 + ((k & 7) >> 1))) * 16)
            + ((n >> 3) & 1) * 8 + ((k >> 3) & 1) * 4 + (k & 1) * 2;
        *reinterpret_cast<__nv_bfloat16*>(base + off) = __float2bfloat16(vals[j]);
    }
}

// ---------------------------------------------------------------------------
// Main kernel: 64x256 CTA tile, 8 warps in 2(M)x4(N) grid, warp tile 32x64.
// A via SMEM (swizzle + ldmatrix, double-buffered); B direct from L2 in
// fragment order: pairs{0,1} distance-1 prefetch, pairs{2,3} JIT per step.
// 2 independent CTAs/SM. Fused softmax epilogue.
// ---------------------------------------------------------------------------
__global__ void __launch_bounds__(256, 2)
cluster_hmma_kernel(const float* __restrict__ batch, float* __restrict__ out) {
    extern __shared__ char smem[];
    const unsigned sb = smem_u32(smem);
    const int tid  = threadIdx.x;
    const int lane = tid & 31;
    const int w    = tid >> 5;
    const int m0   = blockIdx.x * M_TILE;

    const int rowGroup = (w & 1) * 32;        // warp's 32 rows
    const int colGroup = (w >> 1) * 64;       // warp's 64 centroid cols

    // A producer: 4 threads per row, 16 floats each
    const int arow = tid >> 2;
    const int aq   = tid & 3;
    const unsigned axor = (unsigned)((arow & 7) << 4);
    const float* aptr = batch + (size_t)(m0 + arow) * DDIM + aq * 16;

    float psq = 0.f;
    float acc[2][8][4];
    #pragma unroll
    for (int mt = 0; mt < 2; mt++)
        #pragma unroll
        for (int nt = 0; nt < 8; nt++)
            #pragma unroll
            for (int c = 0; c < 4; c++) acc[mt][nt][c] = 0.f;

    auto loadA = [&](int ch, float4 v[4]) {
        const float4* p = reinterpret_cast<const float4*>(aptr + ch * KCHUNK);
        #pragma unroll
        for (int i = 0; i < 4; i++) v[i] = p[i];
    };
    auto storeA = [&](unsigned base, float4 v[4]) {
        #pragma unroll
        for (int i = 0; i < 4; i++)
            psq += v[i].x * v[i].x + v[i].y * v[i].y +
                   v[i].z * v[i].z + v[i].w * v[i].w;
        #pragma unroll
        for (int j = 0; j < 2; j++) {
            __nv_bfloat162 p0 = __floats2bfloat162_rn(v[2*j].x,   v[2*j].y);
            __nv_bfloat162 p1 = __floats2bfloat162_rn(v[2*j].z,   v[2*j].w);
            __nv_bfloat162 p2 = __floats2bfloat162_rn(v[2*j+1].x, v[2*j+1].y);
            __nv_bfloat162 p3 = __floats2bfloat162_rn(v[2*j+1].z, v[2*j+1].w);
            uint4 pk;
            pk.x = *reinterpret_cast<unsigned*>(&p0);
            pk.y = *reinterpret_cast<unsigned*>(&p1);
            pk.z = *reinterpret_cast<unsigned*>(&p2);
            pk.w = *reinterpret_cast<unsigned*>(&p3);
            unsigned col = (unsigned)(aq * 32 + j * 16) ^ axor;
            sts128(base + (unsigned)(arow * 128) + col, pk);
        }
    };

    // A ldmatrix per-lane base (row&7 is lane-constant)
    const unsigned sxor = (unsigned)((lane & 7) << 4);
    const unsigned aFragBase = (unsigned)((rowGroup + (lane & 15)) * 128);
    const unsigned aKsel = (unsigned)((lane >> 4) * 16);

    // B fragment addressing: warp's 4 ntpairs at step s start at
    // g_bf[s*512 + bbase], +32, +64, +96
    const unsigned bbase = (unsigned)((w >> 1) * 128 + lane);

    // ---- prologue ----
    float4 av[4];
    loadA(0, av);
    storeA(sb, av);
    uint4 b0c = g_bf[bbase];          // step-0 pairs 0,1 (prefetched)
    uint4 b1c = g_bf[bbase + 32];
    __syncthreads();

    #pragma unroll 1
    for (int ch = 0; ch < NCHUNKS; ch++) {
        const unsigned cur = sb + (unsigned)((ch & 1) * A_BYTES);
        const unsigned nxt = sb + (unsigned)(((ch + 1) & 1) * A_BYTES);
        const bool more = (ch < NCHUNKS - 1);

        if (more) loadA(ch + 1, av);       // LDG in flight over compute

        const unsigned aB = cur + aFragBase;

        #pragma unroll
        for (int kk = 0; kk < 4; kk++) {
            const int s = ch * 4 + kk;
            const unsigned sOff = (unsigned)s * 512u + bbase;

            // JIT-load pairs 2,3 of current step (consumed ~16 issues later)
            const uint4 b2 = g_bf[sOff + 64];
            const uint4 b3 = g_bf[sOff + 96];

            // A fragments for this k-step
            const unsigned aCol = ((unsigned)(kk * 32) + aKsel) ^ sxor;
            unsigned af[2][4];
            #pragma unroll
            for (int mt = 0; mt < 2; mt++)
                ldmatrix_x4(af[mt], aB + (unsigned)(mt * 16 * 128) + aCol);

            // first half: pairs 0,1 (prefetched last step)
            #pragma unroll
            for (int mt = 0; mt < 2; mt++) {
                mma_16816(acc[mt][0], af[mt], b0c.x, b0c.y);
                mma_16816(acc[mt][1], af[mt], b0c.z, b0c.w);
                mma_16816(acc[mt][2], af[mt], b1c.x, b1c.y);
                mma_16816(acc[mt][3], af[mt], b1c.z, b1c.w);
            }

            // distance-1 prefetch of next step's pairs 0,1
            const unsigned snext = (unsigned)(s + 1 < 64 ? s + 1 : 63);
            const uint4 b0n = g_bf[snext * 512u + bbase];
            const uint4 b1n = g_bf[snext * 512u + bbase + 32];

            // second half: pairs 2,3 (JIT-loaded at step start)
            #pragma unroll
            for (int mt = 0; mt < 2; mt++) {
                mma_16816(acc[mt][4], af[mt], b2.x, b2.y);
                mma_16816(acc[mt][5], af[mt], b2.z, b2.w);
                mma_16816(acc[mt][6], af[mt], b3.x, b3.y);
                mma_16816(acc[mt][7], af[mt], b3.z, b3.w);
            }
            b0c = b0n;
            b1c = b1n;
        }

        if (more) storeA(nxt, av);
        __syncthreads();
    }

    // ---- row norms (4 producer threads per row) ----
    {
        float tot = psq;
        tot += __shfl_xor_sync(0xFFFFFFFFu, tot, 1);
        tot += __shfl_xor_sync(0xFFFFFFFFu, tot, 2);
        if (aq == 0)
            reinterpret_cast<float*>(smem + SM_NORM)[arow] =
                1.0f / fmaxf(sqrtf(tot), 1e-8f);
    }
    __syncthreads();

    const float* smN = reinterpret_cast<const float*>(smem + SM_NORM);
    float* smP = reinterpret_cast<float*>(smem + SM_PART);
    float* smI = reinterpret_cast<float*>(smem + SM_INV);

    // ---- exp in place + row partial sums over this warp's 64 cols ----
    float rsum[2][2];
    #pragma unroll
    for (int mt = 0; mt < 2; mt++) {
        const int r0 = rowGroup + mt * 16 + (lane >> 2);
        const float in0 = smN[r0], in1 = smN[r0 + 8];
        float s0 = 0.f, s1 = 0.f;
        #pragma unroll
        for (int nt = 0; nt < 8; nt++) {
            float e0 = __expf(acc[mt][nt][0] * in0);
            float e1 = __expf(acc[mt][nt][1] * in0);
            float e2 = __expf(acc[mt][nt][2] * in1);
            float e3 = __expf(acc[mt][nt][3] * in1);
            acc[mt][nt][0] = e0; acc[mt][nt][1] = e1;
            acc[mt][nt][2] = e2; acc[mt][nt][3] = e3;
            s0 += e0 + e1;
            s1 += e2 + e3;
        }
        rsum[mt][0] = s0;
        rsum[mt][1] = s1;
    }
    #pragma unroll
    for (int mt = 0; mt < 2; mt++)
        #pragma unroll
        for (int rh = 0; rh < 2; rh++) {
            float s = rsum[mt][rh];
            s += __shfl_xor_sync(0xFFFFFFFFu, s, 1);
            s += __shfl_xor_sync(0xFFFFFFFFu, s, 2);
            rsum[mt][rh] = s;
        }
    if ((lane & 3) == 0) {
        const int cg = (w >> 1) * 64;
        #pragma unroll
        for (int mt = 0; mt < 2; mt++)
            #pragma unroll
            for (int rh = 0; rh < 2; rh++)
                smP[cg + rowGroup + mt * 16 + (lane >> 2) + 8 * rh] = rsum[mt][rh];
    }
    __syncthreads();
    if (tid < 64)
        smI[tid] = 1.0f /
            (smP[tid] + smP[64 + tid] + smP[128 + tid] + smP[192 + tid]);
    __syncthreads();

    // ---- scaled stores ----
    #pragma unroll
    for (int mt = 0; mt < 2; mt++) {
        const int r0 = rowGroup + mt * 16 + (lane >> 2);
        const float is0 = smI[r0], is1 = smI[r0 + 8];
        float* o0 = out + (size_t)(m0 + r0) * KCENT + colGroup + (lane & 3) * 2;
        float* o1 = o0 + (size_t)8 * KCENT;
        #pragma unroll
        for (int nt = 0; nt < 8; nt++) {
            float2 v0 = make_float2(acc[mt][nt][0] * is0, acc[mt][nt][1] * is0);
            float2 v1 = make_float2(acc[mt][nt][2] * is1, acc[mt][nt][3] * is1);
            *reinterpret_cast<float2*>(o0 + nt * 8) = v0;
            *reinterpret_cast<float2*>(o1 + nt * 8) = v1;
        }
    }
}

// ---------------------------------------------------------------------------
extern "C" void kernel_launch(void* const* d_in, const int* in_sizes, int n_in,
                              void* d_out, int out_size) {
    const float* batch     = (const float*)d_in[0];   // [N, D] fp32
    const float* centroids = (const float*)d_in[1];   // [K, D] fp32
    float* out = (float*)d_out;                       // [N, K] fp32

    centroid_prep_kernel<<<KCENT, 256>>>(centroids);

    cudaFuncSetAttribute(cluster_hmma_kernel,
                         cudaFuncAttributeMaxDynamicSharedMemorySize, SMEM_TOTAL);
    cluster_hmma_kernel<<<N_ROWS / M_TILE, 256, SMEM_TOTAL>>>(batch, out);
}

// round 14
// speedup vs baseline: 1.4613x; 1.4613x over previous
#include <cuda_runtime.h>
#include <cuda_bf16.h>
#include <cstdint>

// Problem constants
#define N_ROWS 131072
#define DDIM   1024
#define KCENT  256
#define M_TILE 32                    // rows per CTA
#define KCHUNK 64                    // bf16 elems per D-chunk (128 B rows)
#define NCHUNKS (DDIM / KCHUNK)      // 16

#define A_BYTES (M_TILE * 128)       // 4096 (one A stage)
#define SM_NORM (2 * A_BYTES)        // float[32]
#define SM_PART (SM_NORM + 128)      // float[8*32]
#define SM_INV  (SM_PART + 1024)     // float[32]
#define SMEM_TOTAL (SM_INV + 128)

// Normalized centroids in mma-fragment order (verified R10/R11):
// uint4 index = step*512 + ntpair*32 + lane   (step = ch*4 + kk, 0..63)
__device__ uint4 g_bf[16 * 4 * 16 * 32];   // 512 KB

// ---------------------------------------------------------------------------
// PTX helpers
// ---------------------------------------------------------------------------
__device__ __forceinline__ unsigned smem_u32(const void* p) {
    return (unsigned)__cvta_generic_to_shared(p);
}
__device__ __forceinline__ void ldmatrix_x4(unsigned r[4], unsigned addr) {
    asm volatile("ldmatrix.sync.aligned.m8n8.x4.shared.b16 {%0,%1,%2,%3}, [%4];"
                 : "=r"(r[0]), "=r"(r[1]), "=r"(r[2]), "=r"(r[3]) : "r"(addr));
}
__device__ __forceinline__ void mma_16816(float d[4], const unsigned a[4],
                                          unsigned b0, unsigned b1) {
    asm volatile(
        "mma.sync.aligned.m16n8k16.row.col.f32.bf16.bf16.f32 "
        "{%0,%1,%2,%3}, {%4,%5,%6,%7}, {%8,%9}, {%0,%1,%2,%3};"
        : "+f"(d[0]), "+f"(d[1]), "+f"(d[2]), "+f"(d[3])
        : "r"(a[0]), "r"(a[1]), "r"(a[2]), "r"(a[3]), "r"(b0), "r"(b1));
}
__device__ __forceinline__ void sts128(unsigned addr, uint4 v) {
    asm volatile("st.shared.v4.b32 [%0], {%1, %2, %3, %4};"
                 :: "r"(addr), "r"(v.x), "r"(v.y), "r"(v.z), "r"(v.w) : "memory");
}

// ---------------------------------------------------------------------------
// Prepass: normalize centroids (fp32) and scatter into fragment layout.
// ---------------------------------------------------------------------------
__global__ void centroid_prep_kernel(const float* __restrict__ cent) {
    int n = blockIdx.x;
    int t = threadIdx.x;
    const float4 v = reinterpret_cast<const float4*>(cent + (size_t)n * DDIM)[t];
    float s = v.x * v.x + v.y * v.y + v.z * v.z + v.w * v.w;
    #pragma unroll
    for (int o = 16; o; o >>= 1) s += __shfl_xor_sync(0xFFFFFFFFu, s, o);
    __shared__ float ws[8];
    __shared__ float s_inv;
    if ((t & 31) == 0) ws[t >> 5] = s;
    __syncthreads();
    if (t == 0) {
        float tot = 0.f;
        #pragma unroll
        for (int i = 0; i < 8; i++) tot += ws[i];
        s_inv = 1.0f / fmaxf(sqrtf(tot), 1e-8f);
    }
    __syncthreads();
    const float iv = s_inv;
    float vals[4] = {v.x * iv, v.y * iv, v.z * iv, v.w * iv};
    char* base = reinterpret_cast<char*>(g_bf);
    #pragma unroll
    for (int j = 0; j < 4; j++) {
        int k = t * 4 + j;
        unsigned off =
            (((((unsigned)(k >> 6) * 4 + ((k >> 4) & 3)) * 16 + (n >> 4)) * 32
              + ((n & 7) * 4 + ((k & 7) >> 1))) * 16)
            + ((n >> 3) & 1) * 8 + ((k >> 3) & 1) * 4 + (k & 1) * 2;
        *reinterpret_cast<__nv_bfloat16*>(base + off) = __float2bfloat16(vals[j]);
    }
}

// ---------------------------------------------------------------------------
// Main kernel: 32x256 CTA tile, 8 warps (1x8), warp tile 32x32.
// A via SMEM (swizzle + ldmatrix, double-buffered); B direct from L2 in
// fragment order with FULL distance-1 register prefetch (R11 schedule).
// 3 independent CTAs/SM. Fused softmax epilogue.
// ---------------------------------------------------------------------------
__global__ void __launch_bounds__(256, 3)
cluster_hmma_kernel(const float* __restrict__ batch, float* __restrict__ out) {
    extern __shared__ char smem[];
    const unsigned sb = smem_u32(smem);
    const int tid  = threadIdx.x;
    const int lane = tid & 31;
    const int w    = tid >> 5;
    const int m0   = blockIdx.x * M_TILE;

    const int colGroup = w * 32;          // warp's 32 centroid columns

    // A producer: 8 threads per row, 8 floats each
    const int arow = tid >> 3;
    const int aq   = tid & 7;
    const unsigned axor = (unsigned)((arow & 7) << 4);
    const float* aptr = batch + (size_t)(m0 + arow) * DDIM + aq * 8;

    float psq = 0.f;
    float acc[2][4][4];
    #pragma unroll
    for (int mt = 0; mt < 2; mt++)
        #pragma unroll
        for (int nt = 0; nt < 4; nt++)
            #pragma unroll
            for (int c = 0; c < 4; c++) acc[mt][nt][c] = 0.f;

    auto loadA = [&](int ch, float4 v[2]) {
        const float4* p = reinterpret_cast<const float4*>(aptr + ch * KCHUNK);
        v[0] = p[0];
        v[1] = p[1];
    };
    auto storeA = [&](unsigned base, float4 v[2]) {
        psq += v[0].x * v[0].x + v[0].y * v[0].y + v[0].z * v[0].z + v[0].w * v[0].w
             + v[1].x * v[1].x + v[1].y * v[1].y + v[1].z * v[1].z + v[1].w * v[1].w;
        __nv_bfloat162 p0 = __floats2bfloat162_rn(v[0].x, v[0].y);
        __nv_bfloat162 p1 = __floats2bfloat162_rn(v[0].z, v[0].w);
        __nv_bfloat162 p2 = __floats2bfloat162_rn(v[1].x, v[1].y);
        __nv_bfloat162 p3 = __floats2bfloat162_rn(v[1].z, v[1].w);
        uint4 pk;
        pk.x = *reinterpret_cast<unsigned*>(&p0);
        pk.y = *reinterpret_cast<unsigned*>(&p1);
        pk.z = *reinterpret_cast<unsigned*>(&p2);
        pk.w = *reinterpret_cast<unsigned*>(&p3);
        unsigned col = ((unsigned)(aq * 16)) ^ axor;
        sts128(base + (unsigned)(arow * 128) + col, pk);
    };

    // A ldmatrix per-lane base (row&7 is lane-constant)
    const unsigned sxor = (unsigned)((lane & 7) << 4);
    const unsigned aFragBase = (unsigned)((lane & 15) * 128);
    const unsigned aKsel = (unsigned)((lane >> 4) * 16);

    // B fragment addressing: this warp's two ntpairs at step s live at
    // g_bf[s*512 + bbase] and [+32]
    const unsigned bbase = (unsigned)(w * 2) * 32 + (unsigned)lane;

    // ---- prologue ----
    float4 av[2];
    loadA(0, av);
    storeA(sb, av);
    uint4 b0c = g_bf[bbase];          // step-0 fragments (prefetched)
    uint4 b1c = g_bf[bbase + 32];
    __syncthreads();

    #pragma unroll 1
    for (int ch = 0; ch < NCHUNKS; ch++) {
        const unsigned cur = sb + (unsigned)((ch & 1) * A_BYTES);
        const unsigned nxt = sb + (unsigned)(((ch + 1) & 1) * A_BYTES);
        const bool more = (ch < NCHUNKS - 1);

        if (more) loadA(ch + 1, av);       // LDG in flight over compute

        const unsigned aB = cur + aFragBase;

        #pragma unroll
        for (int kk = 0; kk < 4; kk++) {
            // FULL distance-1 prefetch of next step's B fragments
            const int s = ch * 4 + kk;
            const unsigned snext = (unsigned)(s + 1 < 64 ? s + 1 : 63);
            const uint4 b0n = g_bf[snext * 512u + bbase];
            const uint4 b1n = g_bf[snext * 512u + bbase + 32];

            const unsigned aCol = ((unsigned)(kk * 32) + aKsel) ^ sxor;
            unsigned af[2][4];
            #pragma unroll
            for (int mt = 0; mt < 2; mt++)
                ldmatrix_x4(af[mt], aB + (unsigned)(mt * 16 * 128) + aCol);

            #pragma unroll
            for (int mt = 0; mt < 2; mt++) {
                mma_16816(acc[mt][0], af[mt], b0c.x, b0c.y);
                mma_16816(acc[mt][1], af[mt], b0c.z, b0c.w);
                mma_16816(acc[mt][2], af[mt], b1c.x, b1c.y);
                mma_16816(acc[mt][3], af[mt], b1c.z, b1c.w);
            }
            b0c = b0n;
            b1c = b1n;
        }

        if (more) storeA(nxt, av);
        __syncthreads();
    }

    // ---- row norms (8 producer threads per row) ----
    {
        float tot = psq;
        tot += __shfl_xor_sync(0xFFFFFFFFu, tot, 1);
        tot += __shfl_xor_sync(0xFFFFFFFFu, tot, 2);
        tot += __shfl_xor_sync(0xFFFFFFFFu, tot, 4);
        if (aq == 0)
            reinterpret_cast<float*>(smem + SM_NORM)[arow] =
                1.0f / fmaxf(sqrtf(tot), 1e-8f);
    }
    __syncthreads();

    const float* smN = reinterpret_cast<const float*>(smem + SM_NORM);
    float* smP = reinterpret_cast<float*>(smem + SM_PART);
    float* smI = reinterpret_cast<float*>(smem + SM_INV);

    // ---- exp in place + row partial sums over this warp's 32 cols ----
    float rsum[2][2];
    #pragma unroll
    for (int mt = 0; mt < 2; mt++) {
        const int r0 = mt * 16 + (lane >> 2);
        const float in0 = smN[r0], in1 = smN[r0 + 8];
        float s0 = 0.f, s1 = 0.f;
        #pragma unroll
        for (int nt = 0; nt < 4; nt++) {
            float e0 = __expf(acc[mt][nt][0] * in0);
            float e1 = __expf(acc[mt][nt][1] * in0);
            float e2 = __expf(acc[mt][nt][2] * in1);
            float e3 = __expf(acc[mt][nt][3] * in1);
            acc[mt][nt][0] = e0; acc[mt][nt][1] = e1;
            acc[mt][nt][2] = e2; acc[mt][nt][3] = e3;
            s0 += e0 + e1;
            s1 += e2 + e3;
        }
        rsum[mt][0] = s0;
        rsum[mt][1] = s1;
    }
    #pragma unroll
    for (int mt = 0; mt < 2; mt++)
        #pragma unroll
        for (int rh = 0; rh < 2; rh++) {
            float s = rsum[mt][rh];
            s += __shfl_xor_sync(0xFFFFFFFFu, s, 1);
            s += __shfl_xor_sync(0xFFFFFFFFu, s, 2);
            rsum[mt][rh] = s;
        }
    if ((lane & 3) == 0) {
        #pragma unroll
        for (int mt = 0; mt < 2; mt++)
            #pragma unroll
            for (int rh = 0; rh < 2; rh++)
                smP[w * 32 + mt * 16 + (lane >> 2) + 8 * rh] = rsum[mt][rh];
    }
    __syncthreads();
    if (tid < 32) {
        float s = 0.f;
        #pragma unroll
        for (int g = 0; g < 8; g++) s += smP[g * 32 + tid];
        smI[tid] = 1.0f / s;
    }
    __syncthreads();

    // ---- scaled stores ----
    #pragma unroll
    for (int mt = 0; mt < 2; mt++) {
        const int r0 = mt * 16 + (lane >> 2);
        const float is0 = smI[r0], is1 = smI[r0 + 8];
        float* o0 = out + (size_t)(m0 + r0) * KCENT + colGroup + (lane & 3) * 2;
        float* o1 = o0 + (size_t)8 * KCENT;
        #pragma unroll
        for (int nt = 0; nt < 4; nt++) {
            float2 v0 = make_float2(acc[mt][nt][0] * is0, acc[mt][nt][1] * is0);
            float2 v1 = make_float2(acc[mt][nt][2] * is1, acc[mt][nt][3] * is1);
            *reinterpret_cast<float2*>(o0 + nt * 8) = v0;
            *reinterpret_cast<float2*>(o1 + nt * 8) = v1;
        }
    }
}

// ---------------------------------------------------------------------------
extern "C" void kernel_launch(void* const* d_in, const int* in_sizes, int n_in,
                              void* d_out, int out_size) {
    const float* batch     = (const float*)d_in[0];   // [N, D] fp32
    const float* centroids = (const float*)d_in[1];   // [K, D] fp32
    float* out = (float*)d_out;                       // [N, K] fp32

    centroid_prep_kernel<<<KCENT, 256>>>(centroids);

    cudaFuncSetAttribute(cluster_hmma_kernel,
                         cudaFuncAttributeMaxDynamicSharedMemorySize, SMEM_TOTAL);
    cluster_hmma_kernel<<<N_ROWS / M_TILE, 256, SMEM_TOTAL>>>(batch, out);
}